// round 4
// baseline (speedup 1.0000x reference)
#include <cuda_runtime.h>
#include <math.h>

#define Bb      64
#define Tt      128
#define Dd      768
#define Hh      256
#define NSPANS  8256
#define KTOP    256
#define XST     68          // head/proj stride
#define RST     132         // scorer xs row-stride (128 rows + pad, 16B-aligned)
#define RED_ST  33

typedef unsigned long long u64;

// ---------------- packed fp32x2 helpers (sm_103a FFMA2 path) ----------------
__device__ __forceinline__ u64 dup2(float a) {
    u64 r;
    asm("mov.b64 %0, {%1, %2};" : "=l"(r) : "f"(a), "f"(a));
    return r;
}
__device__ __forceinline__ void fma2(u64& acc, u64 a, u64 b) {
    asm("fma.rn.f32x2 %0, %1, %2, %0;" : "+l"(acc) : "l"(a), "l"(b));
}
__device__ __forceinline__ void unpack2(float& lo, float& hi, u64 v) {
    asm("mov.b64 {%0, %1}, %2;" : "=f"(lo), "=f"(hi) : "l"(v));
}
__device__ __forceinline__ void lds_pair(u64& x, u64& y, const float* p) {
    unsigned addr = (unsigned)__cvta_generic_to_shared(p);
    asm volatile("ld.shared.v2.u64 {%0, %1}, [%2];" : "=l"(x), "=l"(y) : "r"(addr));
}

// ---------------- device scratch ----------------
__device__ float g_A[Bb*Tt*Hh];
__device__ float g_E[Bb*Tt*Hh];
__device__ float g_scores[Bb*NSPANS];
__device__ float g_inj[Bb*Hh];
__device__ int   g_topidx[Bb*KTOP];
__device__ float g_topscore[Bb*KTOP];
__device__ int   g_sarr[NSPANS];
__device__ int   g_earr[NSPANS];

// ---------------- span index decode ----------------
__global__ void build_span_idx_kernel() {
    int n = blockIdx.x * blockDim.x + threadIdx.x;
    if (n >= NSPANS) return;
    int s = 0, off = 0;
    while (n >= off + (Tt - s)) { off += (Tt - s); s++; }
    g_sarr[n] = s;
    g_earr[n] = s + (n - off);
}

// ---------------- projections: X[8192,768]@W[768,256]+b ----------------
__global__ __launch_bounds__(256)
void proj_kernel(const float* __restrict__ X,
                 const float* __restrict__ Wst, const float* __restrict__ bst,
                 const float* __restrict__ Wen, const float* __restrict__ ben) {
    const float* W    = blockIdx.z ? Wen : Wst;
    const float* bias = blockIdx.z ? ben : bst;
    float*       Out  = blockIdx.z ? g_E : g_A;

    __shared__ float xs[32 * RST];
    __shared__ float wsm[32 * XST];

    const int row0 = blockIdx.y * 128;
    const int col0 = blockIdx.x * 64;
    const int tid  = threadIdx.x;
    const int tx   = tid & 15, ty = tid >> 4;

    u64 acc[8][2] = {};

    for (int k0 = 0; k0 < Dd; k0 += 32) {
        __syncthreads();
        #pragma unroll
        for (int idx = tid; idx < 128 * 32; idx += 256) {
            int r = idx >> 5, k = idx & 31;
            xs[k * RST + r] = X[(row0 + r) * Dd + k0 + k];
        }
        #pragma unroll
        for (int idx = tid; idx < 32 * 64; idx += 256) {
            int k = idx >> 6, cc = idx & 63;
            wsm[k * XST + cc] = W[(k0 + k) * Hh + col0 + cc];
        }
        __syncthreads();
        #pragma unroll 4
        for (int k = 0; k < 32; k++) {
            const float4 a0 = *(const float4*)(xs + k * RST + (ty << 3));
            const float4 a1 = *(const float4*)(xs + k * RST + (ty << 3) + 4);
            u64 w0, w1;
            lds_pair(w0, w1, wsm + k * XST + (tx << 2));
            u64 d0 = dup2(a0.x), d1 = dup2(a0.y), d2 = dup2(a0.z), d3 = dup2(a0.w);
            u64 d4 = dup2(a1.x), d5 = dup2(a1.y), d6 = dup2(a1.z), d7 = dup2(a1.w);
            fma2(acc[0][0], d0, w0); fma2(acc[0][1], d0, w1);
            fma2(acc[1][0], d1, w0); fma2(acc[1][1], d1, w1);
            fma2(acc[2][0], d2, w0); fma2(acc[2][1], d2, w1);
            fma2(acc[3][0], d3, w0); fma2(acc[3][1], d3, w1);
            fma2(acc[4][0], d4, w0); fma2(acc[4][1], d4, w1);
            fma2(acc[5][0], d5, w0); fma2(acc[5][1], d5, w1);
            fma2(acc[6][0], d6, w0); fma2(acc[6][1], d6, w1);
            fma2(acc[7][0], d7, w0); fma2(acc[7][1], d7, w1);
        }
    }

    #pragma unroll
    for (int i = 0; i < 8; i++) {
        int row = row0 + (ty << 3) + i;
        #pragma unroll
        for (int p = 0; p < 2; p++) {
            float lo, hi;
            unpack2(lo, hi, acc[i][p]);
            int col = col0 + (tx << 2) + 2 * p;
            Out[row * Hh + col]     = lo + bias[col];
            Out[row * Hh + col + 1] = hi + bias[col + 1];
        }
    }
}

// ---------------- injection projection ----------------
__global__ void inj_kernel(const float* __restrict__ tie,
                           const float* __restrict__ Winj, const float* __restrict__ binj) {
    int b = blockIdx.x;
    int j = threadIdx.x;
    __shared__ float t[128];
    if (j < 128) t[j] = tie[b * 128 + j];
    __syncthreads();
    float acc = binj[j];
    #pragma unroll 8
    for (int k = 0; k < 128; k++) acc = fmaf(t[k], Winj[k * Hh + j], acc);
    g_inj[b * Hh + j] = acc;
}

// ---------------- fused span scorer: 512 threads, 128 spans x 256 cols, 8x8/thread ----------------
// smem: xs[256][RST] + ws[64][256] + bs1c[256] + w2c[256] + red[128][33]
#define SC_SMEM_FLOATS (256*RST + 64*256 + 256 + 256 + 128*RED_ST)
static const int SC_SMEM_BYTES = SC_SMEM_FLOATS * 4;   // 219,648 B

__global__ __launch_bounds__(512, 1)
void scorer_kernel(const float* __restrict__ Ws1, const float* __restrict__ bs1,
                   const float* __restrict__ Ws2, const float* __restrict__ bs2) {
    extern __shared__ float sm[];
    float* xs   = sm;                        // [k=256][r, stride RST]
    float* ws   = xs + 256 * RST;            // [kk=64][c=256]
    float* bs1c = ws + 64 * 256;             // 256
    float* w2c  = bs1c + 256;                // 256
    float* red  = w2c + 256;                 // [128][RED_ST]
    __shared__ int sS[128], sE[128];

    const int b   = blockIdx.y;
    const int n0  = blockIdx.x * 128;
    const int tid = threadIdx.x;
    const int tx  = tid & 31;        // 32 col-groups of 8
    const int ty  = tid >> 5;        // 16 row-groups of 8 (== warp id)

    if (tid < 128) {
        int n = n0 + tid;
        if (n > NSPANS - 1) n = NSPANS - 1;
        sS[tid] = g_sarr[n]; sE[tid] = g_earr[n];
    }
    if (tid < 256) { bs1c[tid] = bs1[tid]; w2c[tid] = Ws2[tid]; }
    __syncthreads();

    // fill xs[k][r] = relu(A[s_r][k] + E[e_r][k]); thread: col k = tid&255, rows half
    {
        const int kcol = tid & 255;
        const int r0f  = (tid >> 8) * 64;
        const float* Ab = g_A + b * Tt * Hh + kcol;
        const float* Eb = g_E + b * Tt * Hh + kcol;
        float* xp = xs + kcol * RST;
        #pragma unroll 4
        for (int r = r0f; r < r0f + 64; r++) {
            float v = Ab[sS[r] * Hh] + Eb[sE[r] * Hh];
            xp[r] = v > 0.f ? v : 0.f;
        }
    }

    u64 acc[8][4] = {};

    #pragma unroll 1
    for (int kc = 0; kc < 4; kc++) {
        const int k0 = kc << 6;
        __syncthreads();
        // stage 64k x 256c weights (float4)
        #pragma unroll
        for (int idx = tid; idx < 4096; idx += 512) {
            int kk = idx >> 6, c4 = idx & 63;
            ((float4*)ws)[idx] = ((const float4*)(Ws1 + (k0 + kk) * Hh))[c4];
        }
        __syncthreads();

        const float* xp = xs + k0 * RST + (ty << 3);
        const float* wp = ws + (tx << 3);
        #pragma unroll 2
        for (int k = 0; k < 64; k++) {
            const float4 a0 = *(const float4*)(xp + k * RST);      // warp-broadcast
            const float4 a1 = *(const float4*)(xp + k * RST + 4);
            u64 w0, w1, w2, w3;
            lds_pair(w0, w1, wp + (k << 8));
            lds_pair(w2, w3, wp + (k << 8) + 4);
            u64 d0 = dup2(a0.x), d1 = dup2(a0.y), d2 = dup2(a0.z), d3 = dup2(a0.w);
            u64 d4 = dup2(a1.x), d5 = dup2(a1.y), d6 = dup2(a1.z), d7 = dup2(a1.w);
            fma2(acc[0][0], d0, w0); fma2(acc[0][1], d0, w1);
            fma2(acc[0][2], d0, w2); fma2(acc[0][3], d0, w3);
            fma2(acc[1][0], d1, w0); fma2(acc[1][1], d1, w1);
            fma2(acc[1][2], d1, w2); fma2(acc[1][3], d1, w3);
            fma2(acc[2][0], d2, w0); fma2(acc[2][1], d2, w1);
            fma2(acc[2][2], d2, w2); fma2(acc[2][3], d2, w3);
            fma2(acc[3][0], d3, w0); fma2(acc[3][1], d3, w1);
            fma2(acc[3][2], d3, w2); fma2(acc[3][3], d3, w3);
            fma2(acc[4][0], d4, w0); fma2(acc[4][1], d4, w1);
            fma2(acc[4][2], d4, w2); fma2(acc[4][3], d4, w3);
            fma2(acc[5][0], d5, w0); fma2(acc[5][1], d5, w1);
            fma2(acc[5][2], d5, w2); fma2(acc[5][3], d5, w3);
            fma2(acc[6][0], d6, w0); fma2(acc[6][1], d6, w1);
            fma2(acc[6][2], d6, w2); fma2(acc[6][3], d6, w3);
            fma2(acc[7][0], d7, w0); fma2(acc[7][1], d7, w1);
            fma2(acc[7][2], d7, w2); fma2(acc[7][3], d7, w3);
        }
    }

    // layer-2 epilogue (single pass, all 256 cols in acc)
    float scacc[8] = {0.f, 0.f, 0.f, 0.f, 0.f, 0.f, 0.f, 0.f};
    #pragma unroll
    for (int i = 0; i < 8; i++) {
        #pragma unroll
        for (int p = 0; p < 4; p++) {
            float lo, hi;
            unpack2(lo, hi, acc[i][p]);
            int cb = (tx << 3) + 2 * p;
            float h0 = lo + bs1c[cb];
            if (h0 > 0.f) scacc[i] = fmaf(h0, w2c[cb], scacc[i]);
            float h1 = hi + bs1c[cb + 1];
            if (h1 > 0.f) scacc[i] = fmaf(h1, w2c[cb + 1], scacc[i]);
        }
    }

    __syncthreads();
    #pragma unroll
    for (int i = 0; i < 8; i++) red[((ty << 3) + i) * RED_ST + tx] = scacc[i];
    __syncthreads();
    if (tid < 128 && n0 + tid < NSPANS) {
        float ssum = bs2[0];
        const float* rp = red + tid * RED_ST;
        #pragma unroll
        for (int t = 0; t < 32; t++) ssum += rp[t];
        g_scores[b * NSPANS + n0 + tid] = ssum;
    }
}

// ---------------- per-batch radix top-k, parallel stable extraction ----------------
__global__ void topk_kernel(const int* __restrict__ mask) {
    const int b   = blockIdx.x;
    const int tid = threadIdx.x;
    __shared__ unsigned keys[NSPANS];
    __shared__ int hist[256];
    __shared__ unsigned sh_prefix;
    __shared__ int sh_kk;
    __shared__ int sgt[256], seqv[256];

    const int* mb = mask + b * Tt;
    for (int i = tid; i < NSPANS; i += 256) {
        int s = g_sarr[i], e = g_earr[i];
        float v = (mb[s] != 0 && mb[e] != 0) ? g_scores[b * NSPANS + i]
                                             : __int_as_float(0xff800000);
        unsigned u = __float_as_uint(v);
        keys[i] = (u & 0x80000000u) ? ~u : (u | 0x80000000u);
    }

    unsigned prefix = 0;
    int kk = KTOP;
    for (int level = 3; level >= 0; level--) {
        hist[tid] = 0;
        __syncthreads();
        const unsigned himask = (level == 3) ? 0u : (0xFFFFFFFFu << ((level + 1) * 8));
        for (int i = tid; i < NSPANS; i += 256) {
            unsigned kv = keys[i];
            if ((kv & himask) == (prefix & himask))
                atomicAdd(&hist[(kv >> (level * 8)) & 255], 1);
        }
        __syncthreads();
        if (tid == 0) {
            int cum = 0, chosen = 0, kknew = kk;
            for (int t = 255; t >= 0; t--) {
                int c = hist[t];
                if (cum + c >= kk) { chosen = t; kknew = kk - cum; break; }
                cum += c;
            }
            sh_prefix = prefix | ((unsigned)chosen << (level * 8));
            sh_kk = kknew;
        }
        __syncthreads();
        prefix = sh_prefix;
        kk = sh_kk;
        __syncthreads();
    }

    const unsigned Kstar = prefix;
    const int CH = (NSPANS + 255) / 256;
    int lo = tid * CH; if (lo > NSPANS) lo = NSPANS;
    int hi = lo + CH;  if (hi > NSPANS) hi = NSPANS;

    int cgt = 0, ceq = 0;
    for (int i = lo; i < hi; i++) {
        unsigned kv = keys[i];
        cgt += (kv > Kstar);
        ceq += (kv == Kstar);
    }
    sgt[tid] = cgt; seqv[tid] = ceq;
    __syncthreads();
    if (tid == 0) {
        int ag = 0, ae = 0;
        for (int t = 0; t < 256; t++) {
            int g = sgt[t], e = seqv[t];
            sgt[t] = ag; seqv[t] = ae;
            ag += g; ae += e;
        }
    }
    __syncthreads();

    int gtb = sgt[tid], eqb = seqv[tid];
    for (int i = lo; i < hi; i++) {
        unsigned kv = keys[i];
        bool isgt = (kv > Kstar);
        bool iseq = (kv == Kstar);
        if (isgt || (iseq && eqb < kk)) {
            int eqt = eqb < kk ? eqb : kk;
            int pos = gtb + eqt;
            unsigned u = (kv & 0x80000000u) ? (kv & 0x7FFFFFFFu) : ~kv;
            g_topidx[b * KTOP + pos]   = i;
            g_topscore[b * KTOP + pos] = __uint_as_float(u);
        }
        gtb += isgt;
        eqb += iseq;
    }
}

// ---------------- fused head ----------------
#define HD_SMEM_FLOATS (256*XST + 256*128 + 128 + 128 + 64*16)
static const int HD_SMEM_BYTES = HD_SMEM_FLOATS * 4;

__global__ __launch_bounds__(256, 1)
void head_kernel(const float* __restrict__ Wsec, const float* __restrict__ bsec,
                 const float* __restrict__ Wpred, const float* __restrict__ bpred,
                 const int* __restrict__ mask, float* __restrict__ out) {
    extern __shared__ float sm[];
    float* xs  = sm;
    float* ws  = xs + 256 * XST;
    float* bc  = ws + 256 * 128;
    float* wpc = bc + 128;
    float* red = wpc + 128;
    __shared__ int sS[64], sE[64];
    __shared__ float sMask[64], sScore[64];

    const int b   = blockIdx.y;
    const int k0  = blockIdx.x * 64;
    const int tid = threadIdx.x;
    const int tx  = tid & 15, ty = tid >> 4;

    if (tid < 64) {
        int n = g_topidx[b * KTOP + k0 + tid];
        int s = g_sarr[n], e = g_earr[n];
        sS[tid] = s; sE[tid] = e;
        sMask[tid] = (mask[b * Tt + s] != 0 && mask[b * Tt + e] != 0) ? 1.f : 0.f;
        float sc = g_topscore[b * KTOP + k0 + tid];
        sScore[tid] = isinf(sc) ? -1.f : sc;
    }
    __syncthreads();

    const float* Ab = g_A + b * Tt * Hh;
    const float* Eb = g_E + b * Tt * Hh;
    for (int r = 0; r < 64; r++)
        xs[tid * XST + r] = Ab[sS[r] * Hh + tid] + Eb[sE[r] * Hh + tid];

    float scacc[4] = {0.f, 0.f, 0.f, 0.f};

    #pragma unroll 1
    for (int jb = 0; jb < 2; jb++) {
        const int jbase = jb * 128;
        __syncthreads();
        #pragma unroll
        for (int idx = tid; idx < 8192; idx += 256) {
            int k = idx >> 5, c4 = idx & 31;
            ((float4*)ws)[idx] = ((const float4*)(Wsec + k * Hh + jbase))[c4];
        }
        if (tid < 128) {
            bc[tid]  = bsec[jbase + tid] + g_inj[b * Hh + jbase + tid];
            wpc[tid] = Wpred[jbase + tid];
        }
        __syncthreads();

        u64 acc[4][4] = {};
        const float* xp = xs + (ty << 2);
        const float* wl = ws + (tx << 2);
        const float* wh = wl + 64;
        #pragma unroll 4
        for (int k = 0; k < Hh; k++) {
            const float4 a = *(const float4*)(xp + k * XST);
            u64 w0, w1, w2, w3;
            lds_pair(w0, w1, wl + (k << 7));
            lds_pair(w2, w3, wh + (k << 7));
            u64 d0 = dup2(a.x), d1 = dup2(a.y), d2 = dup2(a.z), d3 = dup2(a.w);
            fma2(acc[0][0], d0, w0); fma2(acc[0][1], d0, w1);
            fma2(acc[0][2], d0, w2); fma2(acc[0][3], d0, w3);
            fma2(acc[1][0], d1, w0); fma2(acc[1][1], d1, w1);
            fma2(acc[1][2], d1, w2); fma2(acc[1][3], d1, w3);
            fma2(acc[2][0], d2, w0); fma2(acc[2][1], d2, w1);
            fma2(acc[2][2], d2, w2); fma2(acc[2][3], d2, w3);
            fma2(acc[3][0], d3, w0); fma2(acc[3][1], d3, w1);
            fma2(acc[3][2], d3, w2); fma2(acc[3][3], d3, w3);
        }
        #pragma unroll
        for (int i = 0; i < 4; i++) {
            #pragma unroll
            for (int p = 0; p < 4; p++) {
                float lo, hi;
                unpack2(lo, hi, acc[i][p]);
                int cb = (p < 2) ? ((tx << 2) + 2 * p) : (64 + (tx << 2) + 2 * (p - 2));
                float h0 = lo + bc[cb];
                if (h0 > 0.f) scacc[i] = fmaf(h0, wpc[cb], scacc[i]);
                float h1 = hi + bc[cb + 1];
                if (h1 > 0.f) scacc[i] = fmaf(h1, wpc[cb + 1], scacc[i]);
            }
        }
    }

    __syncthreads();
    #pragma unroll
    for (int i = 0; i < 4; i++) red[((ty << 2) + i) * 16 + tx] = scacc[i];
    __syncthreads();
    if (tid < 64) {
        float ssum = bpred[0] + sScore[tid];
        #pragma unroll
        for (int t = 0; t < 16; t++) ssum += red[tid * 16 + t];
        float p = 1.f / (1.f + expf(-ssum));
        out[b * KTOP + k0 + tid] = p * sMask[tid];
    }
}

// ---------------- launch ----------------
extern "C" void kernel_launch(void* const* d_in, const int* in_sizes, int n_in,
                              void* d_out, int out_size) {
    const float* inputs   = (const float*)d_in[0];
    const int*   in_mask  = (const int*)  d_in[1];
    const float* tie      = (const float*)d_in[2];
    const float* W_start  = (const float*)d_in[3];
    const float* b_start  = (const float*)d_in[4];
    const float* W_end    = (const float*)d_in[5];
    const float* b_end    = (const float*)d_in[6];
    const float* W_s1     = (const float*)d_in[7];
    const float* b_s1     = (const float*)d_in[8];
    const float* W_s2     = (const float*)d_in[9];
    const float* b_s2     = (const float*)d_in[10];
    const float* W_inj    = (const float*)d_in[11];
    const float* b_inj    = (const float*)d_in[12];
    const float* W_sec    = (const float*)d_in[13];
    const float* b_sec    = (const float*)d_in[14];
    const float* W_pred   = (const float*)d_in[15];
    const float* b_pred   = (const float*)d_in[16];
    float* out = (float*)d_out;

    cudaFuncSetAttribute(scorer_kernel, cudaFuncAttributeMaxDynamicSharedMemorySize, SC_SMEM_BYTES);
    cudaFuncSetAttribute(head_kernel,   cudaFuncAttributeMaxDynamicSharedMemorySize, HD_SMEM_BYTES);

    build_span_idx_kernel<<<(NSPANS + 255) / 256, 256>>>();
    proj_kernel<<<dim3(Hh / 64, (Bb * Tt) / 128, 2), 256>>>(inputs, W_start, b_start, W_end, b_end);
    inj_kernel<<<Bb, 256>>>(tie, W_inj, b_inj);
    scorer_kernel<<<dim3((NSPANS + 127) / 128, Bb), 512, SC_SMEM_BYTES>>>(W_s1, b_s1, W_s2, b_s2);
    topk_kernel<<<Bb, 256>>>(in_mask);
    head_kernel<<<dim3(KTOP / 64, Bb), 256, HD_SMEM_BYTES>>>(W_sec, b_sec, W_pred, b_pred, in_mask, out);
}

// round 5
// speedup vs baseline: 1.0615x; 1.0615x over previous
#include <cuda_runtime.h>
#include <math.h>

#define Bb      64
#define Tt      128
#define Dd      768
#define Hh      256
#define NSPANS  8256
#define KTOP    256
#define XST     68          // head/proj stride
#define RST     132         // scorer xs row-stride
#define RED_ST  33

typedef unsigned long long u64;

// ---------------- packed fp32x2 helpers (sm_103a FFMA2 path) ----------------
__device__ __forceinline__ u64 dup2(float a) {
    u64 r;
    asm("mov.b64 %0, {%1, %2};" : "=l"(r) : "f"(a), "f"(a));
    return r;
}
__device__ __forceinline__ void fma2(u64& acc, u64 a, u64 b) {
    asm("fma.rn.f32x2 %0, %1, %2, %0;" : "+l"(acc) : "l"(a), "l"(b));
}
__device__ __forceinline__ void unpack2(float& lo, float& hi, u64 v) {
    asm("mov.b64 {%0, %1}, %2;" : "=f"(lo), "=f"(hi) : "l"(v));
}
__device__ __forceinline__ void lds_pair(u64& x, u64& y, const float* p) {
    unsigned addr = (unsigned)__cvta_generic_to_shared(p);
    asm volatile("ld.shared.v2.u64 {%0, %1}, [%2];" : "=l"(x), "=l"(y) : "r"(addr));
}

// ---------------- device scratch ----------------
__device__ float g_A[Bb*Tt*Hh];
__device__ float g_E[Bb*Tt*Hh];
__device__ float g_scores[Bb*NSPANS];
__device__ float g_inj[Bb*Hh];
__device__ int   g_topidx[Bb*KTOP];
__device__ float g_topscore[Bb*KTOP];
__device__ int   g_sarr[NSPANS];
__device__ int   g_earr[NSPANS];

// ---------------- span index decode ----------------
__global__ void build_span_idx_kernel() {
    int n = blockIdx.x * blockDim.x + threadIdx.x;
    if (n >= NSPANS) return;
    int s = 0, off = 0;
    while (n >= off + (Tt - s)) { off += (Tt - s); s++; }
    g_sarr[n] = s;
    g_earr[n] = s + (n - off);
}

// ---------------- projections: X[8192,768]@W[768,256]+b ----------------
__global__ __launch_bounds__(256)
void proj_kernel(const float* __restrict__ X,
                 const float* __restrict__ Wst, const float* __restrict__ bst,
                 const float* __restrict__ Wen, const float* __restrict__ ben) {
    const float* W    = blockIdx.z ? Wen : Wst;
    const float* bias = blockIdx.z ? ben : bst;
    float*       Out  = blockIdx.z ? g_E : g_A;

    __shared__ float xs[32 * RST];
    __shared__ float wsm[32 * XST];

    const int row0 = blockIdx.y * 128;
    const int col0 = blockIdx.x * 64;
    const int tid  = threadIdx.x;
    const int tx   = tid & 15, ty = tid >> 4;

    u64 acc[8][2] = {};

    for (int k0 = 0; k0 < Dd; k0 += 32) {
        __syncthreads();
        #pragma unroll
        for (int idx = tid; idx < 128 * 32; idx += 256) {
            int r = idx >> 5, k = idx & 31;
            xs[k * RST + r] = X[(row0 + r) * Dd + k0 + k];
        }
        #pragma unroll
        for (int idx = tid; idx < 32 * 64; idx += 256) {
            int k = idx >> 6, cc = idx & 63;
            wsm[k * XST + cc] = W[(k0 + k) * Hh + col0 + cc];
        }
        __syncthreads();
        #pragma unroll 4
        for (int k = 0; k < 32; k++) {
            const float4 a0 = *(const float4*)(xs + k * RST + (ty << 3));
            const float4 a1 = *(const float4*)(xs + k * RST + (ty << 3) + 4);
            u64 w0, w1;
            lds_pair(w0, w1, wsm + k * XST + (tx << 2));
            u64 d0 = dup2(a0.x), d1 = dup2(a0.y), d2 = dup2(a0.z), d3 = dup2(a0.w);
            u64 d4 = dup2(a1.x), d5 = dup2(a1.y), d6 = dup2(a1.z), d7 = dup2(a1.w);
            fma2(acc[0][0], d0, w0); fma2(acc[0][1], d0, w1);
            fma2(acc[1][0], d1, w0); fma2(acc[1][1], d1, w1);
            fma2(acc[2][0], d2, w0); fma2(acc[2][1], d2, w1);
            fma2(acc[3][0], d3, w0); fma2(acc[3][1], d3, w1);
            fma2(acc[4][0], d4, w0); fma2(acc[4][1], d4, w1);
            fma2(acc[5][0], d5, w0); fma2(acc[5][1], d5, w1);
            fma2(acc[6][0], d6, w0); fma2(acc[6][1], d6, w1);
            fma2(acc[7][0], d7, w0); fma2(acc[7][1], d7, w1);
        }
    }

    #pragma unroll
    for (int i = 0; i < 8; i++) {
        int row = row0 + (ty << 3) + i;
        #pragma unroll
        for (int p = 0; p < 2; p++) {
            float lo, hi;
            unpack2(lo, hi, acc[i][p]);
            int col = col0 + (tx << 2) + 2 * p;
            Out[row * Hh + col]     = lo + bias[col];
            Out[row * Hh + col + 1] = hi + bias[col + 1];
        }
    }
}

// ---------------- injection projection ----------------
__global__ void inj_kernel(const float* __restrict__ tie,
                           const float* __restrict__ Winj, const float* __restrict__ binj) {
    int b = blockIdx.x;
    int j = threadIdx.x;
    __shared__ float t[128];
    if (j < 128) t[j] = tie[b * 128 + j];
    __syncthreads();
    float acc = binj[j];
    #pragma unroll 8
    for (int k = 0; k < 128; k++) acc = fmaf(t[k], Winj[k * Hh + j], acc);
    g_inj[b * Hh + j] = acc;
}

// ---------------- fused span scorer: 512 thr, 128 spans x 256 cols, 8x8/thread ----------------
// weights split into wsL/wsH halves so per-lane read stride is 16B (conflict-free)
#define SC_SMEM_FLOATS (256*RST + 64*256 + 256 + 256 + 128*RED_ST)
static const int SC_SMEM_BYTES = SC_SMEM_FLOATS * 4;   // 219,648 B

__global__ __launch_bounds__(512, 1)
void scorer_kernel(const float* __restrict__ Ws1, const float* __restrict__ bs1,
                   const float* __restrict__ Ws2, const float* __restrict__ bs2) {
    extern __shared__ float sm[];
    float* xs   = sm;                        // [k=256][r, stride RST]
    float* wsL  = xs + 256 * RST;            // [kk=64][128] cols 8g..8g+3
    float* wsH  = wsL + 64 * 128;            // [kk=64][128] cols 8g+4..8g+7
    float* bs1c = wsH + 64 * 128;            // 256
    float* w2c  = bs1c + 256;                // 256
    float* red  = w2c + 256;                 // [128][RED_ST]
    __shared__ int sS[128], sE[128];

    const int b   = blockIdx.y;
    const int n0  = blockIdx.x * 128;
    const int tid = threadIdx.x;
    const int tx  = tid & 31;        // 32 col-groups of 8
    const int ty  = tid >> 5;        // 16 row-groups of 8

    if (tid < 128) {
        int n = n0 + tid;
        if (n > NSPANS - 1) n = NSPANS - 1;
        sS[tid] = g_sarr[n]; sE[tid] = g_earr[n];
    }
    if (tid < 256) { bs1c[tid] = bs1[tid]; w2c[tid] = Ws2[tid]; }
    __syncthreads();

    // fill xs[k][r] = relu(A[s_r][k] + E[e_r][k])
    {
        const int kcol = tid & 255;
        const int r0f  = (tid >> 8) * 64;
        const float* Ab = g_A + b * Tt * Hh + kcol;
        const float* Eb = g_E + b * Tt * Hh + kcol;
        float* xp = xs + kcol * RST;
        #pragma unroll 4
        for (int r = r0f; r < r0f + 64; r++) {
            float v = Ab[sS[r] * Hh] + Eb[sE[r] * Hh];
            xp[r] = v > 0.f ? v : 0.f;
        }
    }

    u64 acc[8][4] = {};

    #pragma unroll 1
    for (int kc = 0; kc < 4; kc++) {
        const int k0 = kc << 6;
        __syncthreads();
        // stage 64k x 256c weights, even/odd float4 split into wsL/wsH
        #pragma unroll
        for (int idx = tid; idx < 4096; idx += 512) {
            int kk = idx >> 6, c4 = idx & 63;
            float4 f = ((const float4*)(Ws1 + (k0 + kk) * Hh))[c4];
            float4* dst = (c4 & 1) ? (float4*)wsH : (float4*)wsL;
            dst[kk * 32 + (c4 >> 1)] = f;
        }
        __syncthreads();

        const float* xp = xs + k0 * RST + (ty << 3);
        const float* wl = wsL + (tx << 2);
        const float* wh = wsH + (tx << 2);
        #pragma unroll 2
        for (int k = 0; k < 64; k++) {
            const float4 a0 = *(const float4*)(xp + k * RST);      // broadcast
            const float4 a1 = *(const float4*)(xp + k * RST + 4);
            u64 w0, w1, w2, w3;
            lds_pair(w0, w1, wl + (k << 7));   // 16B/lane stride, conflict-free
            lds_pair(w2, w3, wh + (k << 7));
            u64 d0 = dup2(a0.x), d1 = dup2(a0.y), d2 = dup2(a0.z), d3 = dup2(a0.w);
            u64 d4 = dup2(a1.x), d5 = dup2(a1.y), d6 = dup2(a1.z), d7 = dup2(a1.w);
            fma2(acc[0][0], d0, w0); fma2(acc[0][1], d0, w1);
            fma2(acc[0][2], d0, w2); fma2(acc[0][3], d0, w3);
            fma2(acc[1][0], d1, w0); fma2(acc[1][1], d1, w1);
            fma2(acc[1][2], d1, w2); fma2(acc[1][3], d1, w3);
            fma2(acc[2][0], d2, w0); fma2(acc[2][1], d2, w1);
            fma2(acc[2][2], d2, w2); fma2(acc[2][3], d2, w3);
            fma2(acc[3][0], d3, w0); fma2(acc[3][1], d3, w1);
            fma2(acc[3][2], d3, w2); fma2(acc[3][3], d3, w3);
            fma2(acc[4][0], d4, w0); fma2(acc[4][1], d4, w1);
            fma2(acc[4][2], d4, w2); fma2(acc[4][3], d4, w3);
            fma2(acc[5][0], d5, w0); fma2(acc[5][1], d5, w1);
            fma2(acc[5][2], d5, w2); fma2(acc[5][3], d5, w3);
            fma2(acc[6][0], d6, w0); fma2(acc[6][1], d6, w1);
            fma2(acc[6][2], d6, w2); fma2(acc[6][3], d6, w3);
            fma2(acc[7][0], d7, w0); fma2(acc[7][1], d7, w1);
            fma2(acc[7][2], d7, w2); fma2(acc[7][3], d7, w3);
        }
    }

    // layer-2 epilogue; col mapping: acc[i][p] -> cols 8tx+2p, 8tx+2p+1 (split layout preserves it)
    float scacc[8] = {0.f, 0.f, 0.f, 0.f, 0.f, 0.f, 0.f, 0.f};
    #pragma unroll
    for (int i = 0; i < 8; i++) {
        #pragma unroll
        for (int p = 0; p < 4; p++) {
            float lo, hi;
            unpack2(lo, hi, acc[i][p]);
            int cb = (tx << 3) + 2 * p;
            float h0 = lo + bs1c[cb];
            if (h0 > 0.f) scacc[i] = fmaf(h0, w2c[cb], scacc[i]);
            float h1 = hi + bs1c[cb + 1];
            if (h1 > 0.f) scacc[i] = fmaf(h1, w2c[cb + 1], scacc[i]);
        }
    }

    __syncthreads();
    #pragma unroll
    for (int i = 0; i < 8; i++) red[((ty << 3) + i) * RED_ST + tx] = scacc[i];
    __syncthreads();
    if (tid < 128 && n0 + tid < NSPANS) {
        float ssum = bs2[0];
        const float* rp = red + tid * RED_ST;
        #pragma unroll
        for (int t = 0; t < 32; t++) ssum += rp[t];
        g_scores[b * NSPANS + n0 + tid] = ssum;
    }
}

// ---------------- per-batch radix top-k, parallel stable extraction ----------------
__global__ void topk_kernel(const int* __restrict__ mask) {
    const int b   = blockIdx.x;
    const int tid = threadIdx.x;
    __shared__ unsigned keys[NSPANS];
    __shared__ int hist[256];
    __shared__ unsigned sh_prefix;
    __shared__ int sh_kk;
    __shared__ int sgt[256], seqv[256];

    const int* mb = mask + b * Tt;
    for (int i = tid; i < NSPANS; i += 256) {
        int s = g_sarr[i], e = g_earr[i];
        float v = (mb[s] != 0 && mb[e] != 0) ? g_scores[b * NSPANS + i]
                                             : __int_as_float(0xff800000);
        unsigned u = __float_as_uint(v);
        keys[i] = (u & 0x80000000u) ? ~u : (u | 0x80000000u);
    }

    unsigned prefix = 0;
    int kk = KTOP;
    for (int level = 3; level >= 0; level--) {
        hist[tid] = 0;
        __syncthreads();
        const unsigned himask = (level == 3) ? 0u : (0xFFFFFFFFu << ((level + 1) * 8));
        for (int i = tid; i < NSPANS; i += 256) {
            unsigned kv = keys[i];
            if ((kv & himask) == (prefix & himask))
                atomicAdd(&hist[(kv >> (level * 8)) & 255], 1);
        }
        __syncthreads();
        if (tid == 0) {
            int cum = 0, chosen = 0, kknew = kk;
            for (int t = 255; t >= 0; t--) {
                int c = hist[t];
                if (cum + c >= kk) { chosen = t; kknew = kk - cum; break; }
                cum += c;
            }
            sh_prefix = prefix | ((unsigned)chosen << (level * 8));
            sh_kk = kknew;
        }
        __syncthreads();
        prefix = sh_prefix;
        kk = sh_kk;
        __syncthreads();
    }

    const unsigned Kstar = prefix;
    const int CH = (NSPANS + 255) / 256;
    int lo = tid * CH; if (lo > NSPANS) lo = NSPANS;
    int hi = lo + CH;  if (hi > NSPANS) hi = NSPANS;

    int cgt = 0, ceq = 0;
    for (int i = lo; i < hi; i++) {
        unsigned kv = keys[i];
        cgt += (kv > Kstar);
        ceq += (kv == Kstar);
    }
    sgt[tid] = cgt; seqv[tid] = ceq;
    __syncthreads();
    if (tid == 0) {
        int ag = 0, ae = 0;
        for (int t = 0; t < 256; t++) {
            int g = sgt[t], e = seqv[t];
            sgt[t] = ag; seqv[t] = ae;
            ag += g; ae += e;
        }
    }
    __syncthreads();

    int gtb = sgt[tid], eqb = seqv[tid];
    for (int i = lo; i < hi; i++) {
        unsigned kv = keys[i];
        bool isgt = (kv > Kstar);
        bool iseq = (kv == Kstar);
        if (isgt || (iseq && eqb < kk)) {
            int eqt = eqb < kk ? eqb : kk;
            int pos = gtb + eqt;
            unsigned u = (kv & 0x80000000u) ? (kv & 0x7FFFFFFFu) : ~kv;
            g_topidx[b * KTOP + pos]   = i;
            g_topscore[b * KTOP + pos] = __uint_as_float(u);
        }
        gtb += isgt;
        eqb += iseq;
    }
}

// ---------------- fused head ----------------
#define HD_SMEM_FLOATS (256*XST + 256*128 + 128 + 128 + 64*16)
static const int HD_SMEM_BYTES = HD_SMEM_FLOATS * 4;

__global__ __launch_bounds__(256, 1)
void head_kernel(const float* __restrict__ Wsec, const float* __restrict__ bsec,
                 const float* __restrict__ Wpred, const float* __restrict__ bpred,
                 const int* __restrict__ mask, float* __restrict__ out) {
    extern __shared__ float sm[];
    float* xs  = sm;
    float* ws  = xs + 256 * XST;
    float* bc  = ws + 256 * 128;
    float* wpc = bc + 128;
    float* red = wpc + 128;
    __shared__ int sS[64], sE[64];
    __shared__ float sMask[64], sScore[64];

    const int b   = blockIdx.y;
    const int k0  = blockIdx.x * 64;
    const int tid = threadIdx.x;
    const int tx  = tid & 15, ty = tid >> 4;

    if (tid < 64) {
        int n = g_topidx[b * KTOP + k0 + tid];
        int s = g_sarr[n], e = g_earr[n];
        sS[tid] = s; sE[tid] = e;
        sMask[tid] = (mask[b * Tt + s] != 0 && mask[b * Tt + e] != 0) ? 1.f : 0.f;
        float sc = g_topscore[b * KTOP + k0 + tid];
        sScore[tid] = isinf(sc) ? -1.f : sc;
    }
    __syncthreads();

    const float* Ab = g_A + b * Tt * Hh;
    const float* Eb = g_E + b * Tt * Hh;
    for (int r = 0; r < 64; r++)
        xs[tid * XST + r] = Ab[sS[r] * Hh + tid] + Eb[sE[r] * Hh + tid];

    float scacc[4] = {0.f, 0.f, 0.f, 0.f};

    #pragma unroll 1
    for (int jb = 0; jb < 2; jb++) {
        const int jbase = jb * 128;
        __syncthreads();
        #pragma unroll
        for (int idx = tid; idx < 8192; idx += 256) {
            int k = idx >> 5, c4 = idx & 31;
            ((float4*)ws)[idx] = ((const float4*)(Wsec + k * Hh + jbase))[c4];
        }
        if (tid < 128) {
            bc[tid]  = bsec[jbase + tid] + g_inj[b * Hh + jbase + tid];
            wpc[tid] = Wpred[jbase + tid];
        }
        __syncthreads();

        u64 acc[4][4] = {};
        const float* xp = xs + (ty << 2);
        const float* wl = ws + (tx << 2);
        const float* wh = wl + 64;
        #pragma unroll 4
        for (int k = 0; k < Hh; k++) {
            const float4 a = *(const float4*)(xp + k * XST);
            u64 w0, w1, w2, w3;
            lds_pair(w0, w1, wl + (k << 7));
            lds_pair(w2, w3, wh + (k << 7));
            u64 d0 = dup2(a.x), d1 = dup2(a.y), d2 = dup2(a.z), d3 = dup2(a.w);
            fma2(acc[0][0], d0, w0); fma2(acc[0][1], d0, w1);
            fma2(acc[0][2], d0, w2); fma2(acc[0][3], d0, w3);
            fma2(acc[1][0], d1, w0); fma2(acc[1][1], d1, w1);
            fma2(acc[1][2], d1, w2); fma2(acc[1][3], d1, w3);
            fma2(acc[2][0], d2, w0); fma2(acc[2][1], d2, w1);
            fma2(acc[2][2], d2, w2); fma2(acc[2][3], d2, w3);
            fma2(acc[3][0], d3, w0); fma2(acc[3][1], d3, w1);
            fma2(acc[3][2], d3, w2); fma2(acc[3][3], d3, w3);
        }
        #pragma unroll
        for (int i = 0; i < 4; i++) {
            #pragma unroll
            for (int p = 0; p < 4; p++) {
                float lo, hi;
                unpack2(lo, hi, acc[i][p]);
                int cb = (p < 2) ? ((tx << 2) + 2 * p) : (64 + (tx << 2) + 2 * (p - 2));
                float h0 = lo + bc[cb];
                if (h0 > 0.f) scacc[i] = fmaf(h0, wpc[cb], scacc[i]);
                float h1 = hi + bc[cb + 1];
                if (h1 > 0.f) scacc[i] = fmaf(h1, wpc[cb + 1], scacc[i]);
            }
        }
    }

    __syncthreads();
    #pragma unroll
    for (int i = 0; i < 4; i++) red[((ty << 2) + i) * 16 + tx] = scacc[i];
    __syncthreads();
    if (tid < 64) {
        float ssum = bpred[0] + sScore[tid];
        #pragma unroll
        for (int t = 0; t < 16; t++) ssum += red[tid * 16 + t];
        float p = 1.f / (1.f + expf(-ssum));
        out[b * KTOP + k0 + tid] = p * sMask[tid];
    }
}

// ---------------- launch ----------------
extern "C" void kernel_launch(void* const* d_in, const int* in_sizes, int n_in,
                              void* d_out, int out_size) {
    const float* inputs   = (const float*)d_in[0];
    const int*   in_mask  = (const int*)  d_in[1];
    const float* tie      = (const float*)d_in[2];
    const float* W_start  = (const float*)d_in[3];
    const float* b_start  = (const float*)d_in[4];
    const float* W_end    = (const float*)d_in[5];
    const float* b_end    = (const float*)d_in[6];
    const float* W_s1     = (const float*)d_in[7];
    const float* b_s1     = (const float*)d_in[8];
    const float* W_s2     = (const float*)d_in[9];
    const float* b_s2     = (const float*)d_in[10];
    const float* W_inj    = (const float*)d_in[11];
    const float* b_inj    = (const float*)d_in[12];
    const float* W_sec    = (const float*)d_in[13];
    const float* b_sec    = (const float*)d_in[14];
    const float* W_pred   = (const float*)d_in[15];
    const float* b_pred   = (const float*)d_in[16];
    float* out = (float*)d_out;

    cudaFuncSetAttribute(scorer_kernel, cudaFuncAttributeMaxDynamicSharedMemorySize, SC_SMEM_BYTES);
    cudaFuncSetAttribute(head_kernel,   cudaFuncAttributeMaxDynamicSharedMemorySize, HD_SMEM_BYTES);

    build_span_idx_kernel<<<(NSPANS + 255) / 256, 256>>>();
    proj_kernel<<<dim3(Hh / 64, (Bb * Tt) / 128, 2), 256>>>(inputs, W_start, b_start, W_end, b_end);
    inj_kernel<<<Bb, 256>>>(tie, W_inj, b_inj);
    scorer_kernel<<<dim3((NSPANS + 127) / 128, Bb), 512, SC_SMEM_BYTES>>>(W_s1, b_s1, W_s2, b_s2);
    topk_kernel<<<Bb, 256>>>(in_mask);
    head_kernel<<<dim3(KTOP / 64, Bb), 256, HD_SMEM_BYTES>>>(W_sec, b_sec, W_pred, b_pred, in_mask, out);
}

// round 7
// speedup vs baseline: 1.0756x; 1.0133x over previous
#include <cuda_runtime.h>
#include <math.h>

#define Bb      64
#define Tt      128
#define Dd      768
#define Hh      256
#define NSPANS  8256
#define KTOP    256
#define XST     68          // head/proj stride
#define RST     132         // proj xs row-stride
#define SXST    68          // scorer xs row-stride (64 rows + pad, 16B-aligned)

typedef unsigned long long u64;

// ---------------- packed fp32x2 helpers (sm_103a FFMA2 path) ----------------
__device__ __forceinline__ u64 dup2(float a) {
    u64 r; asm("mov.b64 %0, {%1, %2};" : "=l"(r) : "f"(a), "f"(a)); return r;
}
__device__ __forceinline__ void fma2(u64& acc, u64 a, u64 b) {
    asm("fma.rn.f32x2 %0, %1, %2, %0;" : "+l"(acc) : "l"(a), "l"(b));
}
__device__ __forceinline__ void unpack2(float& lo, float& hi, u64 v) {
    asm("mov.b64 {%0, %1}, %2;" : "=f"(lo), "=f"(hi) : "l"(v));
}
__device__ __forceinline__ void lds_pair(u64& x, u64& y, const float* p) {
    unsigned addr = (unsigned)__cvta_generic_to_shared(p);
    asm volatile("ld.shared.v2.u64 {%0, %1}, [%2];" : "=l"(x), "=l"(y) : "r"(addr));
}

// ---------------- device scratch ----------------
__device__ float g_A[Bb*Tt*Hh];
__device__ float g_E[Bb*Tt*Hh];
__device__ float g_scores[Bb*NSPANS];
__device__ float g_inj[Bb*Hh];
__device__ int   g_topidx[Bb*KTOP];
__device__ float g_topscore[Bb*KTOP];
__device__ int   g_sarr[NSPANS];
__device__ int   g_earr[NSPANS];

// ---------------- span index decode ----------------
__global__ void build_span_idx_kernel() {
    int n = blockIdx.x * blockDim.x + threadIdx.x;
    if (n >= NSPANS) return;
    int s = 0, off = 0;
    while (n >= off + (Tt - s)) { off += (Tt - s); s++; }
    g_sarr[n] = s;
    g_earr[n] = s + (n - off);
}

// ---------------- projections: X[8192,768]@W[768,256]+b ----------------
__global__ __launch_bounds__(256)
void proj_kernel(const float* __restrict__ X,
                 const float* __restrict__ Wst, const float* __restrict__ bst,
                 const float* __restrict__ Wen, const float* __restrict__ ben) {
    const float* W    = blockIdx.z ? Wen : Wst;
    const float* bias = blockIdx.z ? ben : bst;
    float*       Out  = blockIdx.z ? g_E : g_A;

    __shared__ float xs[32 * RST];
    __shared__ float wsm[32 * XST];

    const int row0 = blockIdx.y * 128;
    const int col0 = blockIdx.x * 64;
    const int tid  = threadIdx.x;
    const int tx   = tid & 15, ty = tid >> 4;

    u64 acc[8][2] = {};
    for (int k0 = 0; k0 < Dd; k0 += 32) {
        __syncthreads();
        #pragma unroll
        for (int idx = tid; idx < 128 * 32; idx += 256) {
            int r = idx >> 5, k = idx & 31;
            xs[k * RST + r] = X[(row0 + r) * Dd + k0 + k];
        }
        #pragma unroll
        for (int idx = tid; idx < 32 * 64; idx += 256) {
            int k = idx >> 6, cc = idx & 63;
            wsm[k * XST + cc] = W[(k0 + k) * Hh + col0 + cc];
        }
        __syncthreads();
        #pragma unroll 4
        for (int k = 0; k < 32; k++) {
            const float4 a0 = *(const float4*)(xs + k * RST + (ty << 3));
            const float4 a1 = *(const float4*)(xs + k * RST + (ty << 3) + 4);
            u64 w0, w1;
            lds_pair(w0, w1, wsm + k * XST + (tx << 2));
            u64 d0 = dup2(a0.x), d1 = dup2(a0.y), d2 = dup2(a0.z), d3 = dup2(a0.w);
            u64 d4 = dup2(a1.x), d5 = dup2(a1.y), d6 = dup2(a1.z), d7 = dup2(a1.w);
            fma2(acc[0][0], d0, w0); fma2(acc[0][1], d0, w1);
            fma2(acc[1][0], d1, w0); fma2(acc[1][1], d1, w1);
            fma2(acc[2][0], d2, w0); fma2(acc[2][1], d2, w1);
            fma2(acc[3][0], d3, w0); fma2(acc[3][1], d3, w1);
            fma2(acc[4][0], d4, w0); fma2(acc[4][1], d4, w1);
            fma2(acc[5][0], d5, w0); fma2(acc[5][1], d5, w1);
            fma2(acc[6][0], d6, w0); fma2(acc[6][1], d6, w1);
            fma2(acc[7][0], d7, w0); fma2(acc[7][1], d7, w1);
        }
    }
    #pragma unroll
    for (int i = 0; i < 8; i++) {
        int row = row0 + (ty << 3) + i;
        #pragma unroll
        for (int p = 0; p < 2; p++) {
            float lo, hi; unpack2(lo, hi, acc[i][p]);
            int col = col0 + (tx << 2) + 2 * p;
            Out[row * Hh + col]     = lo + bias[col];
            Out[row * Hh + col + 1] = hi + bias[col + 1];
        }
    }
}

// ---------------- injection projection ----------------
__global__ void inj_kernel(const float* __restrict__ tie,
                           const float* __restrict__ Winj, const float* __restrict__ binj) {
    int b = blockIdx.x;
    int j = threadIdx.x;
    __shared__ float t[128];
    if (j < 128) t[j] = tie[b * 128 + j];
    __syncthreads();
    float acc = binj[j];
    #pragma unroll 8
    for (int k = 0; k < 128; k++) acc = fmaf(t[k], Winj[k * Hh + j], acc);
    g_inj[b * Hh + j] = acc;
}

// ---------------- fused span scorer: 256 thr, 64 spans x 256 cols, 2 CTAs/SM ----------------
// dynamic smem: xs[256][SXST] + wsL[32][128] + wsH[32][128] + bias[256] + w2[256]
// red (64 x 33 f32) aliases wsL after last compute chunk.
#define SC_XS_FLOATS   (256 * SXST)
#define SC_WSL_OFF     SC_XS_FLOATS
#define SC_WSH_OFF     (SC_WSL_OFF + 32 * 128)
#define SC_BIAS_OFF    (SC_WSH_OFF + 32 * 128)
#define SC_W2_OFF      (SC_BIAS_OFF + 256)
#define SC_SMEM_FLOATS (SC_W2_OFF + 256)
static const int SC_SMEM_BYTES = SC_SMEM_FLOATS * 4;   // 104,448 B -> 2 CTAs/SM

__global__ __launch_bounds__(256, 2)
void scorer_kernel(const float* __restrict__ Ws1, const float* __restrict__ bs1,
                   const float* __restrict__ Ws2, const float* __restrict__ bs2) {
    extern __shared__ float sm[];
    float* xs   = sm;                        // [k=256][r, stride SXST]
    float* wsL  = sm + SC_WSL_OFF;           // [kk=32][128] cols 8g..8g+3
    float* wsH  = sm + SC_WSH_OFF;           // [kk=32][128] cols 8g+4..8g+7
    float* bs1c = sm + SC_BIAS_OFF;          // 256
    float* w2c  = sm + SC_W2_OFF;            // 256
    float* red  = wsL;                       // aliased: [64][33] after last chunk
    __shared__ int sS[64], sE[64];

    const int b   = blockIdx.y;
    const int n0  = blockIdx.x * 64;
    const int tid = threadIdx.x;
    const int tx  = tid & 31;        // 32 col-groups of 8
    const int ty  = tid >> 5;        // 8 row-groups of 8

    if (tid < 64) {
        sS[tid] = g_sarr[n0 + tid]; sE[tid] = g_earr[n0 + tid];
    }
    bs1c[tid] = bs1[tid];
    w2c[tid]  = Ws2[tid];
    __syncthreads();

    // fill xs[k][r] = relu(A[s_r][k] + E[e_r][k]); thread owns column k = tid
    {
        const float* Ab = g_A + b * Tt * Hh + tid;
        const float* Eb = g_E + b * Tt * Hh + tid;
        float* xp = xs + tid * SXST;
        #pragma unroll 4
        for (int r = 0; r < 64; r++) {
            float v = Ab[sS[r] * Hh] + Eb[sE[r] * Hh];
            xp[r] = v > 0.f ? v : 0.f;
        }
    }

    u64 acc[8][4] = {};

    #pragma unroll 1
    for (int kc = 0; kc < 8; kc++) {
        const int k0 = kc << 5;
        __syncthreads();
        // stage 32k x 256c weights, even/odd float4 split into wsL/wsH
        #pragma unroll
        for (int idx = tid; idx < 2048; idx += 256) {
            int kk = idx >> 6, c4 = idx & 63;
            float4 f = ((const float4*)(Ws1 + (k0 + kk) * Hh))[c4];
            float4* dst = (c4 & 1) ? (float4*)wsH : (float4*)wsL;
            dst[kk * 32 + (c4 >> 1)] = f;
        }
        __syncthreads();

        const float* xp = xs + k0 * SXST + (ty << 3);
        const float* wl = wsL + (tx << 2);
        const float* wh = wsH + (tx << 2);
        #pragma unroll 2
        for (int k = 0; k < 32; k++) {
            const float4 a0 = *(const float4*)(xp + k * SXST);     // broadcast
            const float4 a1 = *(const float4*)(xp + k * SXST + 4);
            u64 w0, w1, w2, w3;
            lds_pair(w0, w1, wl + (k << 7));   // 16B/lane stride, conflict-free
            lds_pair(w2, w3, wh + (k << 7));
            u64 d0 = dup2(a0.x), d1 = dup2(a0.y), d2 = dup2(a0.z), d3 = dup2(a0.w);
            u64 d4 = dup2(a1.x), d5 = dup2(a1.y), d6 = dup2(a1.z), d7 = dup2(a1.w);
            fma2(acc[0][0], d0, w0); fma2(acc[0][1], d0, w1);
            fma2(acc[0][2], d0, w2); fma2(acc[0][3], d0, w3);
            fma2(acc[1][0], d1, w0); fma2(acc[1][1], d1, w1);
            fma2(acc[1][2], d1, w2); fma2(acc[1][3], d1, w3);
            fma2(acc[2][0], d2, w0); fma2(acc[2][1], d2, w1);
            fma2(acc[2][2], d2, w2); fma2(acc[2][3], d2, w3);
            fma2(acc[3][0], d3, w0); fma2(acc[3][1], d3, w1);
            fma2(acc[3][2], d3, w2); fma2(acc[3][3], d3, w3);
            fma2(acc[4][0], d4, w0); fma2(acc[4][1], d4, w1);
            fma2(acc[4][2], d4, w2); fma2(acc[4][3], d4, w3);
            fma2(acc[5][0], d5, w0); fma2(acc[5][1], d5, w1);
            fma2(acc[5][2], d5, w2); fma2(acc[5][3], d5, w3);
            fma2(acc[6][0], d6, w0); fma2(acc[6][1], d6, w1);
            fma2(acc[6][2], d6, w2); fma2(acc[6][3], d6, w3);
            fma2(acc[7][0], d7, w0); fma2(acc[7][1], d7, w1);
            fma2(acc[7][2], d7, w2); fma2(acc[7][3], d7, w3);
        }
    }

    // layer-2 epilogue; acc[i][p] -> cols 8tx+2p, 8tx+2p+1
    float scacc[8] = {0.f, 0.f, 0.f, 0.f, 0.f, 0.f, 0.f, 0.f};
    #pragma unroll
    for (int i = 0; i < 8; i++) {
        #pragma unroll
        for (int p = 0; p < 4; p++) {
            float lo, hi; unpack2(lo, hi, acc[i][p]);
            int cb = (tx << 3) + 2 * p;
            float h0 = lo + bs1c[cb];
            if (h0 > 0.f) scacc[i] = fmaf(h0, w2c[cb], scacc[i]);
            float h1 = hi + bs1c[cb + 1];
            if (h1 > 0.f) scacc[i] = fmaf(h1, w2c[cb + 1], scacc[i]);
        }
    }

    __syncthreads();   // ws no longer needed; red aliases it
    #pragma unroll
    for (int i = 0; i < 8; i++) red[((ty << 3) + i) * 33 + tx] = scacc[i];
    __syncthreads();
    if (tid < 64) {
        float ssum = bs2[0];
        const float* rp = red + tid * 33;
        #pragma unroll
        for (int t = 0; t < 32; t++) ssum += rp[t];
        g_scores[b * NSPANS + n0 + tid] = ssum;
    }
}

// ---------------- per-batch radix top-k, parallel stable extraction ----------------
__global__ void topk_kernel(const int* __restrict__ mask) {
    const int b   = blockIdx.x;
    const int tid = threadIdx.x;
    __shared__ unsigned keys[NSPANS];
    __shared__ int hist[256];
    __shared__ unsigned sh_prefix;
    __shared__ int sh_kk;
    __shared__ int sgt[256], seqv[256];

    const int* mb = mask + b * Tt;
    for (int i = tid; i < NSPANS; i += 256) {
        int s = g_sarr[i], e = g_earr[i];
        float v = (mb[s] != 0 && mb[e] != 0) ? g_scores[b * NSPANS + i]
                                             : __int_as_float(0xff800000);
        unsigned u = __float_as_uint(v);
        keys[i] = (u & 0x80000000u) ? ~u : (u | 0x80000000u);
    }

    unsigned prefix = 0;
    int kk = KTOP;
    for (int level = 3; level >= 0; level--) {
        hist[tid] = 0;
        __syncthreads();
        const unsigned himask = (level == 3) ? 0u : (0xFFFFFFFFu << ((level + 1) * 8));
        for (int i = tid; i < NSPANS; i += 256) {
            unsigned kv = keys[i];
            if ((kv & himask) == (prefix & himask))
                atomicAdd(&hist[(kv >> (level * 8)) & 255], 1);
        }
        __syncthreads();
        if (tid == 0) {
            int cum = 0, chosen = 0, kknew = kk;
            for (int t = 255; t >= 0; t--) {
                int c = hist[t];
                if (cum + c >= kk) { chosen = t; kknew = kk - cum; break; }
                cum += c;
            }
            sh_prefix = prefix | ((unsigned)chosen << (level * 8));
            sh_kk = kknew;
        }
        __syncthreads();
        prefix = sh_prefix;
        kk = sh_kk;
        __syncthreads();
    }

    const unsigned Kstar = prefix;
    const int CH = (NSPANS + 255) / 256;
    int lo = tid * CH; if (lo > NSPANS) lo = NSPANS;
    int hi = lo + CH;  if (hi > NSPANS) hi = NSPANS;

    int cgt = 0, ceq = 0;
    for (int i = lo; i < hi; i++) {
        unsigned kv = keys[i];
        cgt += (kv > Kstar);
        ceq += (kv == Kstar);
    }
    sgt[tid] = cgt; seqv[tid] = ceq;
    __syncthreads();
    if (tid == 0) {
        int ag = 0, ae = 0;
        for (int t = 0; t < 256; t++) {
            int g = sgt[t], e = seqv[t];
            sgt[t] = ag; seqv[t] = ae;
            ag += g; ae += e;
        }
    }
    __syncthreads();

    int gtb = sgt[tid], eqb = seqv[tid];
    for (int i = lo; i < hi; i++) {
        unsigned kv = keys[i];
        bool isgt = (kv > Kstar);
        bool iseq = (kv == Kstar);
        if (isgt || (iseq && eqb < kk)) {
            int eqt = eqb < kk ? eqb : kk;
            int pos = gtb + eqt;
            unsigned u = (kv & 0x80000000u) ? (kv & 0x7FFFFFFFu) : ~kv;
            g_topidx[b * KTOP + pos]   = i;
            g_topscore[b * KTOP + pos] = __uint_as_float(u);
        }
        gtb += isgt;
        eqb += iseq;
    }
}

// ---------------- fused head ----------------
#define HD_SMEM_FLOATS (256*XST + 256*128 + 128 + 128 + 64*16)
static const int HD_SMEM_BYTES = HD_SMEM_FLOATS * 4;

__global__ __launch_bounds__(256, 1)
void head_kernel(const float* __restrict__ Wsec, const float* __restrict__ bsec,
                 const float* __restrict__ Wpred, const float* __restrict__ bpred,
                 const int* __restrict__ mask, float* __restrict__ out) {
    extern __shared__ float sm[];
    float* xs  = sm;
    float* ws  = xs + 256 * XST;
    float* bc  = ws + 256 * 128;
    float* wpc = bc + 128;
    float* red = wpc + 128;
    __shared__ int sS[64], sE[64];
    __shared__ float sMask[64], sScore[64];

    const int b   = blockIdx.y;
    const int k0  = blockIdx.x * 64;
    const int tid = threadIdx.x;
    const int tx  = tid & 15, ty = tid >> 4;

    if (tid < 64) {
        int n = g_topidx[b * KTOP + k0 + tid];
        int s = g_sarr[n], e = g_earr[n];
        sS[tid] = s; sE[tid] = e;
        sMask[tid] = (mask[b * Tt + s] != 0 && mask[b * Tt + e] != 0) ? 1.f : 0.f;
        float sc = g_topscore[b * KTOP + k0 + tid];
        sScore[tid] = isinf(sc) ? -1.f : sc;
    }
    __syncthreads();

    const float* Ab = g_A + b * Tt * Hh;
    const float* Eb = g_E + b * Tt * Hh;
    for (int r = 0; r < 64; r++)
        xs[tid * XST + r] = Ab[sS[r] * Hh + tid] + Eb[sE[r] * Hh + tid];

    float scacc[4] = {0.f, 0.f, 0.f, 0.f};

    #pragma unroll 1
    for (int jb = 0; jb < 2; jb++) {
        const int jbase = jb * 128;
        __syncthreads();
        #pragma unroll
        for (int idx = tid; idx < 8192; idx += 256) {
            int k = idx >> 5, c4 = idx & 31;
            ((float4*)ws)[idx] = ((const float4*)(Wsec + k * Hh + jbase))[c4];
        }
        if (tid < 128) {
            bc[tid]  = bsec[jbase + tid] + g_inj[b * Hh + jbase + tid];
            wpc[tid] = Wpred[jbase + tid];
        }
        __syncthreads();

        u64 acc[4][4] = {};
        const float* xp = xs + (ty << 2);
        const float* wl = ws + (tx << 2);
        const float* wh = wl + 64;
        #pragma unroll 4
        for (int k = 0; k < Hh; k++) {
            const float4 a = *(const float4*)(xp + k * XST);
            u64 w0, w1, w2, w3;
            lds_pair(w0, w1, wl + (k << 7));
            lds_pair(w2, w3, wh + (k << 7));
            u64 d0 = dup2(a.x), d1 = dup2(a.y), d2 = dup2(a.z), d3 = dup2(a.w);
            fma2(acc[0][0], d0, w0); fma2(acc[0][1], d0, w1);
            fma2(acc[0][2], d0, w2); fma2(acc[0][3], d0, w3);
            fma2(acc[1][0], d1, w0); fma2(acc[1][1], d1, w1);
            fma2(acc[1][2], d1, w2); fma2(acc[1][3], d1, w3);
            fma2(acc[2][0], d2, w0); fma2(acc[2][1], d2, w1);
            fma2(acc[2][2], d2, w2); fma2(acc[2][3], d2, w3);
            fma2(acc[3][0], d3, w0); fma2(acc[3][1], d3, w1);
            fma2(acc[3][2], d3, w2); fma2(acc[3][3], d3, w3);
        }
        #pragma unroll
        for (int i = 0; i < 4; i++) {
            #pragma unroll
            for (int p = 0; p < 4; p++) {
                float lo, hi; unpack2(lo, hi, acc[i][p]);
                int cb = (p < 2) ? ((tx << 2) + 2 * p) : (64 + (tx << 2) + 2 * (p - 2));
                float h0 = lo + bc[cb];
                if (h0 > 0.f) scacc[i] = fmaf(h0, wpc[cb], scacc[i]);
                float h1 = hi + bc[cb + 1];
                if (h1 > 0.f) scacc[i] = fmaf(h1, wpc[cb + 1], scacc[i]);
            }
        }
    }

    __syncthreads();
    #pragma unroll
    for (int i = 0; i < 4; i++) red[((ty << 2) + i) * 16 + tx] = scacc[i];
    __syncthreads();
    if (tid < 64) {
        float ssum = bpred[0] + sScore[tid];
        #pragma unroll
        for (int t = 0; t < 16; t++) ssum += red[tid * 16 + t];
        float p = 1.f / (1.f + expf(-ssum));
        out[b * KTOP + k0 + tid] = p * sMask[tid];
    }
}

// ---------------- launch ----------------
extern "C" void kernel_launch(void* const* d_in, const int* in_sizes, int n_in,
                              void* d_out, int out_size) {
    const float* inputs   = (const float*)d_in[0];
    const int*   in_mask  = (const int*)  d_in[1];
    const float* tie      = (const float*)d_in[2];
    const float* W_start  = (const float*)d_in[3];
    const float* b_start  = (const float*)d_in[4];
    const float* W_end    = (const float*)d_in[5];
    const float* b_end    = (const float*)d_in[6];
    const float* W_s1     = (const float*)d_in[7];
    const float* b_s1     = (const float*)d_in[8];
    const float* W_s2     = (const float*)d_in[9];
    const float* b_s2     = (const float*)d_in[10];
    const float* W_inj    = (const float*)d_in[11];
    const float* b_inj    = (const float*)d_in[12];
    const float* W_sec    = (const float*)d_in[13];
    const float* b_sec    = (const float*)d_in[14];
    const float* W_pred   = (const float*)d_in[15];
    const float* b_pred   = (const float*)d_in[16];
    float* out = (float*)d_out;

    cudaFuncSetAttribute(scorer_kernel, cudaFuncAttributeMaxDynamicSharedMemorySize, SC_SMEM_BYTES);
    cudaFuncSetAttribute(head_kernel,   cudaFuncAttributeMaxDynamicSharedMemorySize, HD_SMEM_BYTES);

    build_span_idx_kernel<<<(NSPANS + 255) / 256, 256>>>();
    proj_kernel<<<dim3(Hh / 64, (Bb * Tt) / 128, 2), 256>>>(inputs, W_start, b_start, W_end, b_end);
    inj_kernel<<<Bb, 256>>>(tie, W_inj, b_inj);
    scorer_kernel<<<dim3(NSPANS / 64, Bb), 256, SC_SMEM_BYTES>>>(W_s1, b_s1, W_s2, b_s2);
    topk_kernel<<<Bb, 256>>>(in_mask);
    head_kernel<<<dim3(KTOP / 64, Bb), 256, HD_SMEM_BYTES>>>(W_sec, b_sec, W_pred, b_pred, in_mask, out);
}